// round 5
// baseline (speedup 1.0000x reference)
#include <cuda_runtime.h>

#define NQ    20
#define NPART 10
#define NB    128          // blocks; each warp owns one column l
#define WPB   8
#define TPB   256

__device__ float    g_partial[NB][1024];
__device__ unsigned g_count;   // zero-init; self-resets via atomicInc wrap

__device__ __forceinline__ float2 cmul(float2 a, float2 b) {
    return make_float2(a.x * b.x - a.y * b.y, a.x * b.y + a.y * b.x);
}
__device__ __forceinline__ float2 cadd(float2 a, float2 b) {
    return make_float2(a.x + b.x, a.y + b.y);
}

__global__ void __launch_bounds__(TPB) sim_kernel(const float* __restrict__ x,
                                                  const float* __restrict__ w,
                                                  float* __restrict__ out) {
    __shared__ float2 sT1[1024];
    __shared__ float2 sT2[1024];
    __shared__ float2 sv[NQ][2];
    __shared__ int    sFB[NQ];
    __shared__ float2 sV[40];
    __shared__ int    sXHlo[32];
    __shared__ float  sacc[WPB][32 * 33];   // padded, conflict-free
    __shared__ unsigned sLast;

    const int tid  = threadIdx.x;
    const int warp = tid >> 5;
    const int lane = tid & 31;

    const float RS2  = 0.70710678118654752440f;   // 1/sqrt(2)
    const float WMUL = 0.63245553203367586640f;   // sqrt(2/5)

    if (tid < NQ) {
        // encoding column v_q = Rz(atan(x^2)) * Ry(atan(x)) * H |0>
        const int q = tid;
        float xq = x[q];
        float th = atanf(xq);
        float c, s;
        sincosf(0.5f * th, &s, &c);
        float a = (c - s) * RS2;
        float b = (c + s) * RS2;
        float ph = 0.5f * atanf(xq * xq);
        float pc, ps;
        sincosf(ph, &ps, &pc);
        sv[q][0] = make_float2(a * pc, -a * ps);
        sv[q][1] = make_float2(b * pc,  b * ps);

        // f = inverse CNOT-ring permutation on basis bit p=tid
        int y = 1 << tid;
        for (int qq = NQ - 1; qq >= 0; --qq) {
            int cb  = 19 - qq;
            int tb2 = 19 - ((qq + 2) % NQ);
            int tb1 = 19 - ((qq + 1) % NQ);
            if ((y >> cb) & 1) y ^= (1 << tb2);
            if ((y >> cb) & 1) y ^= (1 << tb1);
        }
        sFB[tid] = y;
    }

    if (tid < NPART) {
        // fused variational gate V = Rx(w2) * Rz(w1) * Rx(w0), measured qubits
        const int q = tid;
        float w0 = w[3 * q + 0] * WMUL;
        float w1 = w[3 * q + 1] * WMUL;
        float w2 = w[3 * q + 2] * WMUL;
        float c0, s0, c1, s1, c2, s2;
        sincosf(0.5f * w0, &s0, &c0);
        sincosf(0.5f * w1, &s1, &c1);
        sincosf(0.5f * w2, &s2, &c2);
        float2 r00 = make_float2(c0, 0.f), r01 = make_float2(0.f, -s0);
        float2 d0  = make_float2(c1, -s1), d1  = make_float2(c1,  s1);
        float2 A00 = cmul(d0, r00), A01 = cmul(d0, r01);
        float2 A10 = cmul(d1, r01), A11 = cmul(d1, r00);
        float2 m = make_float2(0.f, -s2);
        sV[4 * q + 0] = cadd(make_float2(c2 * A00.x, c2 * A00.y), cmul(m, A10));
        sV[4 * q + 1] = cadd(make_float2(c2 * A01.x, c2 * A01.y), cmul(m, A11));
        sV[4 * q + 2] = cadd(cmul(m, A00), make_float2(c2 * A10.x, c2 * A10.y));
        sV[4 * q + 3] = cadd(cmul(m, A01), make_float2(c2 * A11.x, c2 * A11.y));
    }
    __syncthreads();

    // product tables (4 entries per thread) + low-bit XOR basis table
#pragma unroll
    for (int a = tid; a < 1024; a += TPB) {
        float2 p1 = make_float2(1.f, 0.f);
        float2 p2 = make_float2(1.f, 0.f);
#pragma unroll
        for (int q = 0; q < NPART; ++q)
            p1 = cmul(p1, sv[q][(a >> (9 - q)) & 1]);
#pragma unroll
        for (int q = NPART; q < NQ; ++q)
            p2 = cmul(p2, sv[q][(a >> (19 - q)) & 1]);
        sT1[a] = p1;
        sT2[a] = p2;
    }
    if (tid < 32) {
        int v = 0;
#pragma unroll
        for (int i = 0; i < 5; ++i)
            if ((tid >> i) & 1) v ^= sFB[10 + i];
        sXHlo[tid] = v;
    }
    __syncthreads();

    // ---- this warp's column
    const int l = blockIdx.x * WPB + warp;
    int xl = 0;
#pragma unroll
    for (int j = 0; j < 10; ++j)
        if ((l >> j) & 1) xl ^= sFB[j];
    int xhhi = 0;
#pragma unroll
    for (int p = 0; p < 5; ++p)
        if ((lane >> p) & 1) xhhi ^= sFB[15 + p];
    const int xbase = xhhi ^ xl;

    // synthesize 32 amps/thread: h = (lane<<5) | r
    float2 a[32];
#pragma unroll
    for (int r = 0; r < 32; ++r) {
        int xx = xbase ^ sXHlo[r];
        a[r] = cmul(sT1[xx >> 10], sT2[xx & 1023]);
    }

    // 5 register stages: h bit b (b=0..4), gate q = 9-b
#pragma unroll
    for (int b = 0; b < 5; ++b) {
        const int q = 9 - b;
        float2 V00 = sV[4 * q + 0], V01 = sV[4 * q + 1];
        float2 V10 = sV[4 * q + 2], V11 = sV[4 * q + 3];
#pragma unroll
        for (int g = 0; g < 16; ++g) {
            int lo = g & ((1 << b) - 1);
            int r0 = ((g >> b) << (b + 1)) | lo;
            int r1 = r0 | (1 << b);
            float2 a0 = a[r0];
            float2 a1 = a[r1];
            a[r0] = cadd(cmul(V00, a0), cmul(V01, a1));
            a[r1] = cadd(cmul(V10, a0), cmul(V11, a1));
        }
    }

    // 5 shuffle stages: h bit 5+p (lane bit p), gate q = 4-p
#pragma unroll
    for (int p = 0; p < 5; ++p) {
        const int q = 4 - p;
        float2 V00 = sV[4 * q + 0], V01 = sV[4 * q + 1];
        float2 V10 = sV[4 * q + 2], V11 = sV[4 * q + 3];
        const int bit = (lane >> p) & 1;
        const float2 Vs = bit ? V11 : V00;
        const float2 Vo = bit ? V10 : V01;
#pragma unroll
        for (int r = 0; r < 32; ++r) {
            float2 o;
            o.x = __shfl_xor_sync(0xffffffffu, a[r].x, 1 << p);
            o.y = __shfl_xor_sync(0xffffffffu, a[r].y, 1 << p);
            a[r] = cadd(cmul(Vs, a[r]), cmul(Vo, o));
        }
    }

    // |amp|^2 into padded per-warp shared slice
#pragma unroll
    for (int r = 0; r < 32; ++r)
        sacc[warp][lane * 33 + r] = a[r].x * a[r].x + a[r].y * a[r].y;
    __syncthreads();

    // deterministic block reduce over the 8 warps -> per-block partial
#pragma unroll
    for (int h = tid; h < 1024; h += TPB) {
        const int lh = h >> 5;
        const int rr = h & 31;
        float s = 0.f;
#pragma unroll
        for (int ww = 0; ww < WPB; ++ww)
            s += sacc[ww][lh * 33 + rr];
        g_partial[blockIdx.x][h] = s;
    }

    // ---- fused cross-block reduction: last arriving block sums everything.
    __threadfence();
    if (tid == 0) {
        unsigned old = atomicInc(&g_count, NB - 1);   // wraps to 0 on last
        sLast = (old == NB - 1) ? 1u : 0u;
    }
    __syncthreads();
    if (sLast) {
        __threadfence();   // acquire: all partials visible
        const float4* P = (const float4*)g_partial;   // [NB][256]
        const int c = tid;                            // 0..255 float4 columns
        float4 s = make_float4(0.f, 0.f, 0.f, 0.f);
#pragma unroll 16
        for (int b = 0; b < NB; ++b) {
            float4 v = P[b * 256 + c];
            s.x += v.x; s.y += v.y; s.z += v.z; s.w += v.w;
        }
        ((float4*)out)[c] = s;
    }
}

extern "C" void kernel_launch(void* const* d_in, const int* in_sizes, int n_in,
                              void* d_out, int out_size) {
    const float* x = (const float*)d_in[0];   // (1, 20) float32
    const float* w = (const float*)d_in[1];   // (60,)  float32
    float* out = (float*)d_out;               // (1, 1024) float32

    sim_kernel<<<NB, TPB>>>(x, w, out);
}

// round 6
// speedup vs baseline: 1.1858x; 1.1858x over previous
#include <cuda_runtime.h>

#define NQ    20
#define NPART 10
#define NB    128          // sim blocks
#define TPB   512          // 16 warps = 8 warp-pairs = 8 columns per block

__device__ __forceinline__ float2 cmul(float2 a, float2 b) {
    return make_float2(a.x * b.x - a.y * b.y, a.x * b.y + a.y * b.x);
}
__device__ __forceinline__ float2 cadd(float2 a, float2 b) {
    return make_float2(a.x + b.x, a.y + b.y);
}

// full 2x2 complex butterfly (scalar FFMA form)
__device__ __forceinline__ void bfly(float2& A0, float2& A1,
                                     float2 V00, float2 V01, float2 V10, float2 V11) {
    float2 a0 = A0, a1 = A1;
    A0 = cadd(cmul(V00, a0), cmul(V01, a1));
    A1 = cadd(cmul(V10, a0), cmul(V11, a1));
}

// swizzled exchange address (bijection on 0..1023, conflict-friendly)
__device__ __forceinline__ int xaddr(int h) {
    int row = h >> 4, col = h & 15;
    return row * 16 + (col ^ (row & 15));
}

// ---------------------------------------------------------------------------
// 128 blocks x 512 threads; each warp-PAIR owns one column l.
// 16 float2 amps/thread: 4 reg stages (h bits 0-3) -> pair-local smem
// exchange -> 2 shfl stages (bits 4-5) -> 4 reg stages (bits 6-9) ->
// |amp|^2 -> block reduce over 8 columns -> RED.F32 atomicAdd into out.
// ---------------------------------------------------------------------------
__global__ void __launch_bounds__(TPB) sim_kernel(const float* __restrict__ x,
                                                  const float* __restrict__ w,
                                                  float* __restrict__ out) {
    extern __shared__ float dynf[];
    // overlay: T1/T2 tables live only until synthesis; staging planes after.
    float2* sT1 = (float2*)dynf;            // [1024]
    float2* sT2 = (float2*)dynf + 1024;     // [1024]
    // staging: column c -> re plane dynf + c*2048, im plane +1024

    __shared__ float2 sv[NQ][2];
    __shared__ int    sFB[NQ];
    __shared__ float2 sV[40];
    __shared__ int    sXR[16];

    const int tid  = threadIdx.x;
    const int warp = tid >> 5;
    const int lane = tid & 31;
    const int c    = warp >> 1;        // column slot 0..7
    const int wp   = warp & 1;         // warp-in-pair
    const int pl   = (wp << 5) | lane; // pair-lane 0..63

    const float RS2  = 0.70710678118654752440f;   // 1/sqrt(2)
    const float WMUL = 0.63245553203367586640f;   // sqrt(2/5)

    if (tid < NQ) {
        // encoding column v_q = Rz(atan(x^2)) * Ry(atan(x)) * H |0>
        const int q = tid;
        float xq = x[q];
        float th = atanf(xq);
        float cc, ss;
        sincosf(0.5f * th, &ss, &cc);
        float a = (cc - ss) * RS2;
        float b = (cc + ss) * RS2;
        float ph = 0.5f * atanf(xq * xq);
        float pc, ps;
        sincosf(ph, &ps, &pc);
        sv[q][0] = make_float2(a * pc, -a * ps);
        sv[q][1] = make_float2(b * pc,  b * ps);

        // f = inverse CNOT-ring permutation on basis bit p=tid
        int y = 1 << tid;
        for (int qq = NQ - 1; qq >= 0; --qq) {
            int cb  = 19 - qq;
            int tb2 = 19 - ((qq + 2) % NQ);
            int tb1 = 19 - ((qq + 1) % NQ);
            if ((y >> cb) & 1) y ^= (1 << tb2);
            if ((y >> cb) & 1) y ^= (1 << tb1);
        }
        sFB[tid] = y;
    }

    if (tid < NPART) {
        // fused variational gate V = Rx(w2) * Rz(w1) * Rx(w0), measured qubits
        const int q = tid;
        float w0 = w[3 * q + 0] * WMUL;
        float w1 = w[3 * q + 1] * WMUL;
        float w2 = w[3 * q + 2] * WMUL;
        float c0, s0, c1, s1, c2, s2;
        sincosf(0.5f * w0, &s0, &c0);
        sincosf(0.5f * w1, &s1, &c1);
        sincosf(0.5f * w2, &s2, &c2);
        float2 r00 = make_float2(c0, 0.f), r01 = make_float2(0.f, -s0);
        float2 d0  = make_float2(c1, -s1), d1  = make_float2(c1,  s1);
        float2 A00 = cmul(d0, r00), A01 = cmul(d0, r01);
        float2 A10 = cmul(d1, r01), A11 = cmul(d1, r00);
        float2 m = make_float2(0.f, -s2);
        sV[4 * q + 0] = cadd(make_float2(c2 * A00.x, c2 * A00.y), cmul(m, A10));
        sV[4 * q + 1] = cadd(make_float2(c2 * A01.x, c2 * A01.y), cmul(m, A11));
        sV[4 * q + 2] = cadd(cmul(m, A00), make_float2(c2 * A10.x, c2 * A10.y));
        sV[4 * q + 3] = cadd(cmul(m, A01), make_float2(c2 * A11.x, c2 * A11.y));
    }
    __syncthreads();

    // product tables (2 entries/thread)
#pragma unroll
    for (int a = tid; a < 1024; a += TPB) {
        float2 p1 = make_float2(1.f, 0.f);
        float2 p2 = make_float2(1.f, 0.f);
#pragma unroll
        for (int q = 0; q < NPART; ++q)
            p1 = cmul(p1, sv[q][(a >> (9 - q)) & 1]);
#pragma unroll
        for (int q = NPART; q < NQ; ++q)
            p2 = cmul(p2, sv[q][(a >> (19 - q)) & 1]);
        sT1[a] = p1;
        sT2[a] = p2;
    }
    if (tid < 16) {
        int v = 0;
#pragma unroll
        for (int i = 0; i < 4; ++i)
            if ((tid >> i) & 1) v ^= sFB[10 + i];
        sXR[tid] = v;
    }
    __syncthreads();

    // ---- this pair's column
    const int l = blockIdx.x * 8 + c;
    int xl = 0;
#pragma unroll
    for (int j = 0; j < 10; ++j)
        if ((l >> j) & 1) xl ^= sFB[j];
    int plx = 0;
#pragma unroll
    for (int p = 0; p < 6; ++p)
        if ((pl >> p) & 1) plx ^= sFB[14 + p];   // h bit 4+p -> global bit 14+p
    const int xbase = xl ^ plx;

    // synthesize 16 amps: h = (pl<<4) | r
    float2 a[16];
#pragma unroll
    for (int r = 0; r < 16; ++r) {
        int xx = xbase ^ sXR[r];
        a[r] = cmul(sT1[xx >> 10], sT2[xx & 1023]);
    }
    __syncthreads();   // all warps done reading tables -> staging may overwrite

    // phase 1: 4 register stages on h bits 0..3 (gates q = 9,8,7,6)
#pragma unroll
    for (int b = 0; b < 4; ++b) {
        const int q = 9 - b;
        float2 V00 = sV[4 * q + 0], V01 = sV[4 * q + 1];
        float2 V10 = sV[4 * q + 2], V11 = sV[4 * q + 3];
#pragma unroll
        for (int g = 0; g < 8; ++g) {
            int lo = g & ((1 << b) - 1);
            int r0 = ((g >> b) << (b + 1)) | lo;
            int r1 = r0 | (1 << b);
            bfly(a[r0], a[r1], V00, V01, V10, V11);
        }
    }

    // pair-local exchange through swizzled re/im planes
    float* sRe = dynf + c * 2048;
    float* sIm = sRe + 1024;
#pragma unroll
    for (int r = 0; r < 16; ++r) {
        int ad = xaddr((pl << 4) | r);
        sRe[ad] = a[r].x;
        sIm[ad] = a[r].y;
    }
    asm volatile("bar.sync %0, %1;" :: "r"(c + 1), "r"(64) : "memory");

    // new assignment: h = (r'<<6)| h[5:4]=lane[1:0], h[3]=wp, h[2:0]=lane[4:2]
    const int base6 = ((lane & 1) << 4) | ((lane & 2) << 4) | (wp << 3)
                    | (((lane >> 4) & 1) << 2) | (((lane >> 3) & 1) << 1) | ((lane >> 2) & 1);
#pragma unroll
    for (int r = 0; r < 16; ++r) {
        int ad = xaddr((r << 6) | base6);
        a[r] = make_float2(sRe[ad], sIm[ad]);
    }
    asm volatile("bar.sync %0, %1;" :: "r"(c + 1), "r"(64) : "memory");

    // 2 shfl stages: h bit4 <-> lane0 (gate q=5), h bit5 <-> lane1 (gate q=4)
#pragma unroll
    for (int p = 0; p < 2; ++p) {
        const int q = 5 - p;
        float2 V00 = sV[4 * q + 0], V01 = sV[4 * q + 1];
        float2 V10 = sV[4 * q + 2], V11 = sV[4 * q + 3];
        const int bitv = (lane >> p) & 1;
        const float2 Vs = bitv ? V11 : V00;
        const float2 Vo = bitv ? V10 : V01;
#pragma unroll
        for (int r = 0; r < 16; ++r) {
            float2 o;
            o.x = __shfl_xor_sync(0xffffffffu, a[r].x, 1 << p);
            o.y = __shfl_xor_sync(0xffffffffu, a[r].y, 1 << p);
            a[r] = cadd(cmul(Vs, a[r]), cmul(Vo, o));
        }
    }

    // phase 2: 4 register stages on h bits 6..9 (gates q = 3,2,1,0)
#pragma unroll
    for (int p = 0; p < 4; ++p) {
        const int q = 3 - p;
        float2 V00 = sV[4 * q + 0], V01 = sV[4 * q + 1];
        float2 V10 = sV[4 * q + 2], V11 = sV[4 * q + 3];
#pragma unroll
        for (int g = 0; g < 8; ++g) {
            int lo = g & ((1 << p) - 1);
            int r0 = ((g >> p) << (p + 1)) | lo;
            int r1 = r0 | (1 << p);
            bfly(a[r0], a[r1], V00, V01, V10, V11);
        }
    }

    // |amp|^2 -> re plane at plain h
#pragma unroll
    for (int r = 0; r < 16; ++r)
        sRe[(r << 6) | base6] = a[r].x * a[r].x + a[r].y * a[r].y;
    __syncthreads();

    // block reduce over the 8 columns, RED.F32 into out (order-insensitive
    // to ~1e-7; tolerance is 1e-3)
#pragma unroll
    for (int h = tid; h < 1024; h += TPB) {
        float s = 0.f;
#pragma unroll
        for (int cc = 0; cc < 8; ++cc)
            s += dynf[cc * 2048 + h];
        atomicAdd(&out[h], s);
    }
}

extern "C" void kernel_launch(void* const* d_in, const int* in_sizes, int n_in,
                              void* d_out, int out_size) {
    const float* x = (const float*)d_in[0];   // (1, 20) float32
    const float* w = (const float*)d_in[1];   // (60,)  float32
    float* out = (float*)d_out;               // (1, 1024) float32

    cudaMemsetAsync(out, 0, 1024 * sizeof(float));
    const int dynsmem = 8 * 2048 * 4;         // 64 KB (tables overlay staging)
    cudaFuncSetAttribute(sim_kernel, cudaFuncAttributeMaxDynamicSharedMemorySize, dynsmem);
    sim_kernel<<<NB, TPB, dynsmem>>>(x, w, out);
}